// round 16
// baseline (speedup 1.0000x reference)
#include <cuda_runtime.h>
#include <cuda_fp16.h>
#include <cstdint>

// ---------------------------------------------------------------------------
// WindowAttention fused (1 CTA = 1 window), FP16 mma m16n8k16 (f32 acc).
// R16: double-buffered QKV smem -> 1 barrier per head-pair (was 2);
// q-scale folded into prepacked weights (uniform branch-free scatter).
// ---------------------------------------------------------------------------

constexpr int NTOK = 49;
constexpr int DIMC = 256;

constexpr int HX = 264;
constexpr int HO = 264;
constexpr int HS = 72;        // q/k/v section stride
constexpr int SEC = 64 * HS;  // 4608 halves per section
constexpr int BUF = 3 * SEC;  // 13824 halves per qkv buffer

constexpr int OFF_X  = 0;                  // 12936 -> pad 12944
constexpr int OFF_B0 = 12944;              // qkv buf0
constexpr int OFF_B1 = OFF_B0 + BUF;       // 26768 qkv buf1
constexpr int OFF_O  = OFF_B1 + BUF;       // 40592
constexpr int HALVES = 53536;              // O ends 53528, align
constexpr int SMEM_BYTES = HALVES * 2 + 256 * 4;   // 108096 B

// W1 fragments: block (hp,kc,kk,nb,nf) of 32 uint4 (q-section pre-scaled)
__device__ uint4  g_w1f[4 * 8 * 2 * 4 * 3 * 32];   // 384 KB
// Wp fragments: block (kc,kk,nb,nf) of 32 uint4
__device__ uint4  g_wpf[8 * 2 * 4 * 4 * 32];        // 128 KB
__device__ __half g_biash[8 * 49 * 64];             // bias[h][row][col] fp16

__global__ void prep_kernel(const float* __restrict__ qkv_w,
                            const float* __restrict__ proj_w,
                            const float* __restrict__ bias_table,
                            const int*   __restrict__ rel_idx) {
    const float scale = 0.17677669529663687f;   // 1/sqrt(32)
    int t = blockIdx.x * blockDim.x + threadIdx.x;
    if (t < 24576) {
        // --- W1 fragment packing (q section pre-scaled) ---
        int lane = t & 31;
        int r2 = t >> 5;
        int nf = r2 % 3;  int r3 = r2 / 3;
        int nb = r3 & 3;  int r4 = r3 >> 2;
        int kk = r4 & 1;  int r5 = r4 >> 1;
        int kc = r5 & 7;  int hp = r5 >> 3;
        int h0 = 2 * hp;
        uint32_t wr[4];
        #pragma unroll
        for (int t4 = 0; t4 < 4; t4++) {
            int rowt = (t4 & 2) ? 8 : 0;
            int coft = (t4 & 1) ? 8 : 0;
            int r  = nb * 48 + nf * 16 + rowt + (lane >> 2);   // 0..191
            int gn = (r >> 6) * 256 + (h0 + ((r & 63) >> 5)) * 32 + (r & 31);
            int k  = kc * 32 + kk * 16 + coft + 2 * (lane & 3);
            float f0 = qkv_w[(size_t)k * 768 + gn];
            float f1 = qkv_w[(size_t)(k + 1) * 768 + gn];
            if (r < 64) { f0 *= scale; f1 *= scale; }   // q section
            __half2 hv = __floats2half2_rn(f0, f1);
            wr[t4] = *(uint32_t*)&hv;
        }
        g_w1f[t] = make_uint4(wr[0], wr[1], wr[2], wr[3]);
    } else if (t < 32768) {
        // --- Wp fragment packing: r2 = (kc*2+kk)*16 + nb*4 + nf ---
        int u = t - 24576;
        int lane = u & 31;
        int r2 = u >> 5;
        int nf = r2 & 3;  int r3 = r2 >> 2;
        int nb = r3 & 3;  int r4 = r3 >> 2;
        int kk = r4 & 1;  int kc = r4 >> 1;
        uint32_t wr[4];
        #pragma unroll
        for (int t4 = 0; t4 < 4; t4++) {
            int rowt = (t4 & 2) ? 8 : 0;
            int coft = (t4 & 1) ? 8 : 0;
            int gn = nb * 64 + nf * 16 + rowt + (lane >> 2);
            int k  = kc * 32 + kk * 16 + coft + 2 * (lane & 3);
            __half2 hv = __floats2half2_rn(proj_w[(size_t)k * 256 + gn],
                                           proj_w[(size_t)(k + 1) * 256 + gn]);
            wr[t4] = *(uint32_t*)&hv;
        }
        g_wpf[u] = make_uint4(wr[0], wr[1], wr[2], wr[3]);
    } else {
        // --- bias matrix (fp16, padding cols = -30000) ---
        int u = t - 32768;
        if (u < 25088) {
            int h = u / 3136, rem = u % 3136;
            int r = rem >> 6, c = rem & 63;
            float v = (c < 49) ? bias_table[rel_idx[r * 49 + c] * 8 + h]
                               : -30000.0f;
            g_biash[u] = __float2half_rn(v);
        }
    }
}

__device__ __forceinline__ void mma16(float c[4],
                                      uint32_t a0, uint32_t a1, uint32_t a2, uint32_t a3,
                                      uint32_t b0, uint32_t b1) {
    asm volatile(
        "mma.sync.aligned.m16n8k16.row.col.f32.f16.f16.f32 "
        "{%0,%1,%2,%3}, {%4,%5,%6,%7}, {%8,%9}, {%0,%1,%2,%3};"
        : "+f"(c[0]), "+f"(c[1]), "+f"(c[2]), "+f"(c[3])
        : "r"(a0), "r"(a1), "r"(a2), "r"(a3), "r"(b0), "r"(b1));
}
__device__ __forceinline__ void ldsm4(uint32_t r[4], uint32_t a) {
    asm volatile("ldmatrix.sync.aligned.m8n8.x4.shared.b16 {%0,%1,%2,%3}, [%4];"
        : "=r"(r[0]), "=r"(r[1]), "=r"(r[2]), "=r"(r[3]) : "r"(a));
}
__device__ __forceinline__ void ldsm4t(uint32_t r[4], uint32_t a) {
    asm volatile("ldmatrix.sync.aligned.m8n8.x4.trans.shared.b16 {%0,%1,%2,%3}, [%4];"
        : "=r"(r[0]), "=r"(r[1]), "=r"(r[2]), "=r"(r[3]) : "r"(a));
}
__device__ __forceinline__ uint32_t packh2(float x, float y) {
    __half2 h = __floats2half2_rn(x, y);
    return *(uint32_t*)&h;
}

__global__ void __launch_bounds__(256, 2)
win_attn_kernel(const float* __restrict__ x,
                const float* __restrict__ proj_b,
                float*       __restrict__ out) {
    extern __shared__ __half sh[];
    __half* s_x = sh + OFF_X;
    __half* s_o = sh + OFF_O;
    float* s_pb = (float*)((char*)sh + HALVES * 2);
    const uint32_t sb = (uint32_t)__cvta_generic_to_shared(sh);

    const int tid  = threadIdx.x;
    const int w    = tid >> 5;
    const int lane = tid & 31;
    const int g    = lane >> 2;
    const int tg   = lane & 3;
    const int b    = blockIdx.x;

    const int mi = w & 1;          // GEMM1/proj 32-row block
    const int nb = w >> 1;         // GEMM1/proj N block
    const int ahh = w >> 2;        // attention: head within pair
    const int R   = (w & 3) * 16;  // attention: row base

    // ldmatrix lane decomposition
    const int arow_in = (lane & 7) | (((lane >> 3) & 1) << 3);
    const int acol8   = (lane >> 4) << 3;
    const int brow_in = (lane & 7) | (((lane >> 4) & 1) << 3);
    const int bcol8   = ((lane >> 3) & 1) << 3;
    const int vrow_in = lane & 15;
    const int vcol8   = (lane >> 4) << 3;

    // ---- init: stage x (f32->half), proj_b ----
    {
        const float4* x4 = (const float4*)(x + (size_t)b * (NTOK * DIMC));
        #pragma unroll
        for (int i = 0; i < 13; i++) {
            int idx = tid + i * 256;
            if (idx < 3136) {
                int r = idx >> 6, c4 = idx & 63;
                float4 v = x4[idx];
                __half2* dst = (__half2*)&s_x[r * HX + c4 * 4];
                dst[0] = __floats2half2_rn(v.x, v.y);
                dst[1] = __floats2half2_rn(v.z, v.w);
            }
        }
        s_pb[tid] = proj_b[tid];
    }

    // precomputed byte addresses
    uint32_t aXb[2];
    #pragma unroll
    for (int mt = 0; mt < 2; mt++) {
        int r = mi * 32 + mt * 16 + arow_in;
        int rc = (r < 49) ? r : 48;
        aXb[mt] = sb + 2 * (OFF_X + rc * HX + acol8);
    }
    // attention bases for buf0; add bufoff per pair
    const uint32_t aQb = sb + 2 * (OFF_B0 + (R + arow_in) * HS + ahh * 32 + acol8);
    uint32_t bKb[4];
    #pragma unroll
    for (int nf = 0; nf < 4; nf++)
        bKb[nf] = sb + 2 * (OFF_B0 + SEC + (nf * 16 + brow_in) * HS + ahh * 32 + bcol8);
    uint32_t bVb[2];
    #pragma unroll
    for (int nf = 0; nf < 2; nf++)
        bVb[nf] = sb + 2 * (OFF_B0 + 2 * SEC + vrow_in * HS + ahh * 32 + nf * 16 + vcol8);
    uint32_t aOb[2];
    #pragma unroll
    for (int mt = 0; mt < 2; mt++) {
        int r = mi * 32 + mt * 16 + arow_in;
        int rc = (r < 49) ? r : 48;
        aOb[mt] = sb + 2 * (OFF_O + rc * HO + acol8);
    }

    // cross-phase prefetch: first GEMM1 B fragments of pair 0
    const uint4* wpB = g_w1f + nb * 96 + lane;
    uint4 bv0 = wpB[0], bv1 = wpB[32], bv2 = wpB[64];

    __syncthreads();

    for (int hp = 0; hp < 4; hp++) {
        const int h0 = 2 * hp;
        const uint32_t bufoff = (uint32_t)(hp & 1) * (BUF * 2);   // bytes
        __half* dbuf = sh + OFF_B0 + (hp & 1) * BUF;

        // ======= GEMM1: qkv_pair[64,192] = x @ W1, B streamed from L2 ======
        float acc1[2][6][4];
        #pragma unroll
        for (int mt = 0; mt < 2; mt++)
            #pragma unroll
            for (int nt = 0; nt < 6; nt++) {
                acc1[mt][nt][0] = 0.f; acc1[mt][nt][1] = 0.f;
                acc1[mt][nt][2] = 0.f; acc1[mt][nt][3] = 0.f;
            }
        {
            const uint4* wp = wpB + (size_t)hp * (16 * 384);
            #pragma unroll
            for (int i = 0; i < 16; i++) {
                uint4 nx0, nx1, nx2;
                if (i < 15) {
                    const uint4* np = wp + (i + 1) * 384;
                    nx0 = np[0]; nx1 = np[32]; nx2 = np[64];
                }
                uint32_t a[2][4];
                ldsm4(a[0], aXb[0] + i * 32);
                ldsm4(a[1], aXb[1] + i * 32);
                mma16(acc1[0][0], a[0][0], a[0][1], a[0][2], a[0][3], bv0.x, bv0.y);
                mma16(acc1[1][0], a[1][0], a[1][1], a[1][2], a[1][3], bv0.x, bv0.y);
                mma16(acc1[0][1], a[0][0], a[0][1], a[0][2], a[0][3], bv0.z, bv0.w);
                mma16(acc1[1][1], a[1][0], a[1][1], a[1][2], a[1][3], bv0.z, bv0.w);
                mma16(acc1[0][2], a[0][0], a[0][1], a[0][2], a[0][3], bv1.x, bv1.y);
                mma16(acc1[1][2], a[1][0], a[1][1], a[1][2], a[1][3], bv1.x, bv1.y);
                mma16(acc1[0][3], a[0][0], a[0][1], a[0][2], a[0][3], bv1.z, bv1.w);
                mma16(acc1[1][3], a[1][0], a[1][1], a[1][2], a[1][3], bv1.z, bv1.w);
                mma16(acc1[0][4], a[0][0], a[0][1], a[0][2], a[0][3], bv2.x, bv2.y);
                mma16(acc1[1][4], a[1][0], a[1][1], a[1][2], a[1][3], bv2.x, bv2.y);
                mma16(acc1[0][5], a[0][0], a[0][1], a[0][2], a[0][3], bv2.z, bv2.w);
                mma16(acc1[1][5], a[1][0], a[1][1], a[1][2], a[1][3], bv2.z, bv2.w);
                if (i < 15) { bv0 = nx0; bv1 = nx1; bv2 = nx2; }
            }
        }
        // scatter q/k/v (uniform: scale pre-folded into weights)
        #pragma unroll
        for (int mt = 0; mt < 2; mt++) {
            const int r0 = mi * 32 + mt * 16 + g, r1 = r0 + 8;
            #pragma unroll
            for (int nt = 0; nt < 6; nt++) {
                const int colb = nb * 48 + nt * 8;
                const int di = (colb >> 6) * SEC + (colb & 63) + 2 * tg;
                *(__half2*)&dbuf[di + r0 * HS] =
                    __floats2half2_rn(acc1[mt][nt][0], acc1[mt][nt][1]);
                *(__half2*)&dbuf[di + r1 * HS] =
                    __floats2half2_rn(acc1[mt][nt][2], acc1[mt][nt][3]);
            }
        }
        __syncthreads();   // qkv visible to all warps

        // ======= scores: warp = 16 rows x 64 cols of one head ==============
        float sacc[8][4];
        #pragma unroll
        for (int nt = 0; nt < 8; nt++) {
            sacc[nt][0] = 0.f; sacc[nt][1] = 0.f;
            sacc[nt][2] = 0.f; sacc[nt][3] = 0.f;
        }
        #pragma unroll
        for (int kk = 0; kk < 2; kk++) {
            const uint32_t kl = kk * 32;
            uint32_t a[4], bfr[4][4];
            ldsm4(a, aQb + bufoff + kl);
            ldsm4(bfr[0], bKb[0] + bufoff + kl);
            ldsm4(bfr[1], bKb[1] + bufoff + kl);
            ldsm4(bfr[2], bKb[2] + bufoff + kl);
            ldsm4(bfr[3], bKb[3] + bufoff + kl);
            #pragma unroll
            for (int nt = 0; nt < 8; nt++)
                mma16(sacc[nt], a[0], a[1], a[2], a[3],
                      bfr[nt >> 1][(nt & 1) * 2], bfr[nt >> 1][(nt & 1) * 2 + 1]);
        }

        // prefetch next pair's first GEMM1 B fragments (hidden by softmax/PV)
        if (hp < 3) {
            const uint4* np = wpB + (size_t)(hp + 1) * (16 * 384);
            bv0 = np[0]; bv1 = np[32]; bv2 = np[64];
        }

        // ======= softmax in registers; fp16 bias from L2-hot table =========
        uint32_t pa[4][4];
        {
            const int head = h0 + ahh;
            const int row0 = R + g, row1 = R + 8 + g;
            const int rs0 = (row0 < 49) ? row0 : 48;
            const int rs1 = (row1 < 49) ? row1 : 48;
            const __half* b0p = g_biash + (head * 49 + rs0) * 64;
            const __half* b1p = g_biash + (head * 49 + rs1) * 64;
            float mx0 = -1e30f, mx1 = -1e30f;
            #pragma unroll
            for (int nt = 0; nt < 8; nt++) {
                const int c0 = nt * 8 + 2 * tg;
                float2 bA = __half22float2(*(const __half2*)(b0p + c0));
                float2 bB = __half22float2(*(const __half2*)(b1p + c0));
                float v;
                v = sacc[nt][0] + bA.x; sacc[nt][0] = v; mx0 = fmaxf(mx0, v);
                v = sacc[nt][1] + bA.y; sacc[nt][1] = v; mx0 = fmaxf(mx0, v);
                v = sacc[nt][2] + bB.x; sacc[nt][2] = v; mx1 = fmaxf(mx1, v);
                v = sacc[nt][3] + bB.y; sacc[nt][3] = v; mx1 = fmaxf(mx1, v);
            }
            mx0 = fmaxf(mx0, __shfl_xor_sync(0xffffffffu, mx0, 1, 4));
            mx0 = fmaxf(mx0, __shfl_xor_sync(0xffffffffu, mx0, 2, 4));
            mx1 = fmaxf(mx1, __shfl_xor_sync(0xffffffffu, mx1, 1, 4));
            mx1 = fmaxf(mx1, __shfl_xor_sync(0xffffffffu, mx1, 2, 4));
            float sum0 = 0.f, sum1 = 0.f;
            #pragma unroll
            for (int nt = 0; nt < 8; nt++) {
                float e;
                e = __expf(sacc[nt][0] - mx0); sacc[nt][0] = e; sum0 += e;
                e = __expf(sacc[nt][1] - mx0); sacc[nt][1] = e; sum0 += e;
                e = __expf(sacc[nt][2] - mx1); sacc[nt][2] = e; sum1 += e;
                e = __expf(sacc[nt][3] - mx1); sacc[nt][3] = e; sum1 += e;
            }
            sum0 += __shfl_xor_sync(0xffffffffu, sum0, 1, 4);
            sum0 += __shfl_xor_sync(0xffffffffu, sum0, 2, 4);
            sum1 += __shfl_xor_sync(0xffffffffu, sum1, 1, 4);
            sum1 += __shfl_xor_sync(0xffffffffu, sum1, 2, 4);
            const float ri0 = 1.0f / sum0, ri1 = 1.0f / sum1;
            #pragma unroll
            for (int kk = 0; kk < 4; kk++) {
                pa[kk][0] = packh2(sacc[2 * kk][0] * ri0, sacc[2 * kk][1] * ri0);
                pa[kk][1] = packh2(sacc[2 * kk][2] * ri1, sacc[2 * kk][3] * ri1);
                pa[kk][2] = packh2(sacc[2 * kk + 1][0] * ri0, sacc[2 * kk + 1][1] * ri0);
                pa[kk][3] = packh2(sacc[2 * kk + 1][2] * ri1, sacc[2 * kk + 1][3] * ri1);
            }
        }

        // ======= O = P @ V (V row-major, trans ldmatrix B-frags) ===========
        {
            float oacc[4][4];
            #pragma unroll
            for (int nt = 0; nt < 4; nt++) {
                oacc[nt][0] = 0.f; oacc[nt][1] = 0.f;
                oacc[nt][2] = 0.f; oacc[nt][3] = 0.f;
            }
            #pragma unroll
            for (int kk = 0; kk < 4; kk++) {
                const uint32_t kl = kk * (16 * HS * 2);   // 16 token rows
                uint32_t bfr[2][4];
                ldsm4t(bfr[0], bVb[0] + bufoff + kl);
                ldsm4t(bfr[1], bVb[1] + bufoff + kl);
                #pragma unroll
                for (int nt = 0; nt < 4; nt++)
                    mma16(oacc[nt], pa[kk][0], pa[kk][1], pa[kk][2], pa[kk][3],
                          bfr[nt >> 1][(nt & 1) * 2], bfr[nt >> 1][(nt & 1) * 2 + 1]);
            }
            const int row0 = R + g, row1 = R + 8 + g;
            const int cb = (h0 + ahh) * 32;
            #pragma unroll
            for (int nt = 0; nt < 4; nt++) {
                const int c = cb + nt * 8 + 2 * tg;
                if (row0 < 49)
                    *(__half2*)&s_o[row0 * HO + c] =
                        __floats2half2_rn(oacc[nt][0], oacc[nt][1]);
                if (row1 < 49)
                    *(__half2*)&s_o[row1 * HO + c] =
                        __floats2half2_rn(oacc[nt][2], oacc[nt][3]);
            }
        }
        // no barrier here: next pair writes the other qkv buffer
    } // head pairs

    // hoist proj B i=0 fragments before the barrier (latency hidden)
    const uint4* wpp = g_wpf + nb * 128 + lane;
    uint4 pv0 = wpp[0], pv1 = wpp[32], pv2 = wpp[64], pv3 = wpp[96];
    __syncthreads();   // s_o complete

    // ======= proj: out = O[64,256] @ Wp + b, B streamed from L2 ============
    {
        float facc[2][8][4];
        #pragma unroll
        for (int mt = 0; mt < 2; mt++)
            #pragma unroll
            for (int j = 0; j < 8; j++) {
                facc[mt][j][0] = 0.f; facc[mt][j][1] = 0.f;
                facc[mt][j][2] = 0.f; facc[mt][j][3] = 0.f;
            }
        #pragma unroll
        for (int i = 0; i < 16; i++) {
            uint4 bv0p = pv0, bv1p = pv1, bv2p = pv2, bv3p = pv3;
            if (i < 15) {
                const uint4* bp = wpp + (i + 1) * 512;
                pv0 = bp[0]; pv1 = bp[32]; pv2 = bp[64]; pv3 = bp[96];
            }
            uint32_t a[2][4];
            ldsm4(a[0], aOb[0] + i * 32);
            ldsm4(a[1], aOb[1] + i * 32);
            mma16(facc[0][0], a[0][0], a[0][1], a[0][2], a[0][3], bv0p.x, bv0p.y);
            mma16(facc[1][0], a[1][0], a[1][1], a[1][2], a[1][3], bv0p.x, bv0p.y);
            mma16(facc[0][1], a[0][0], a[0][1], a[0][2], a[0][3], bv0p.z, bv0p.w);
            mma16(facc[1][1], a[1][0], a[1][1], a[1][2], a[1][3], bv0p.z, bv0p.w);
            mma16(facc[0][2], a[0][0], a[0][1], a[0][2], a[0][3], bv1p.x, bv1p.y);
            mma16(facc[1][2], a[1][0], a[1][1], a[1][2], a[1][3], bv1p.x, bv1p.y);
            mma16(facc[0][3], a[0][0], a[0][1], a[0][2], a[0][3], bv1p.z, bv1p.w);
            mma16(facc[1][3], a[1][0], a[1][1], a[1][2], a[1][3], bv1p.z, bv1p.w);
            mma16(facc[0][4], a[0][0], a[0][1], a[0][2], a[0][3], bv2p.x, bv2p.y);
            mma16(facc[1][4], a[1][0], a[1][1], a[1][2], a[1][3], bv2p.x, bv2p.y);
            mma16(facc[0][5], a[0][0], a[0][1], a[0][2], a[0][3], bv2p.z, bv2p.w);
            mma16(facc[1][5], a[1][0], a[1][1], a[1][2], a[1][3], bv2p.z, bv2p.w);
            mma16(facc[0][6], a[0][0], a[0][1], a[0][2], a[0][3], bv3p.x, bv3p.y);
            mma16(facc[1][6], a[1][0], a[1][1], a[1][2], a[1][3], bv3p.x, bv3p.y);
            mma16(facc[0][7], a[0][0], a[0][1], a[0][2], a[0][3], bv3p.z, bv3p.w);
            mma16(facc[1][7], a[1][0], a[1][1], a[1][2], a[1][3], bv3p.z, bv3p.w);
        }
        // epilogue
        float* ob = out + (size_t)b * (NTOK * DIMC);
        #pragma unroll
        for (int mt = 0; mt < 2; mt++) {
            const int r0 = mi * 32 + mt * 16 + g, r1 = r0 + 8;
            #pragma unroll
            for (int nt = 0; nt < 8; nt++) {
                const int c = nb * 64 + nt * 8 + 2 * tg;
                if (r0 < NTOK) {
                    float2 v;
                    v.x = facc[mt][nt][0] + s_pb[c];
                    v.y = facc[mt][nt][1] + s_pb[c + 1];
                    *(float2*)(ob + r0 * DIMC + c) = v;
                }
                if (r1 < NTOK) {
                    float2 v;
                    v.x = facc[mt][nt][2] + s_pb[c];
                    v.y = facc[mt][nt][3] + s_pb[c + 1];
                    *(float2*)(ob + r1 * DIMC + c) = v;
                }
            }
        }
    }
}

extern "C" void kernel_launch(void* const* d_in, const int* in_sizes, int n_in,
                              void* d_out, int out_size) {
    (void)in_sizes; (void)n_in; (void)out_size;
    const float* x      = (const float*)d_in[0];
    const float* qkv_w  = (const float*)d_in[1];
    const float* proj_w = (const float*)d_in[2];
    const float* proj_b = (const float*)d_in[3];
    const float* bt     = (const float*)d_in[4];
    const int*   ri     = (const int*)d_in[5];
    float* out = (float*)d_out;

    prep_kernel<<<226, 256>>>(qkv_w, proj_w, bt, ri);
    cudaFuncSetAttribute(win_attn_kernel,
                         cudaFuncAttributeMaxDynamicSharedMemorySize, SMEM_BYTES);
    win_attn_kernel<<<4096, 256, SMEM_BYTES>>>(x, proj_b, out);
}

// round 17
// speedup vs baseline: 1.0914x; 1.0914x over previous
#include <cuda_runtime.h>
#include <cuda_fp16.h>
#include <cstdint>

// ---------------------------------------------------------------------------
// WindowAttention fused (1 CTA = 1 window), FP16 mma m16n8k16 (f32 acc).
// R17: R15 base + softmax fast path: scale*log2e folded into q-weights,
// log2e folded into bias, exp2f without max-subtraction, 1/sum deferred
// past PV (sum reduction overlaps PV mma issue).
// ---------------------------------------------------------------------------

constexpr int NTOK = 49;
constexpr int DIMC = 256;

// strides in halves
constexpr int HX  = 264;
constexpr int HQ  = 72;
constexpr int HK  = 72;
constexpr int HV  = 72;   // v row-major [token][dim]
constexpr int HO  = 264;

constexpr int OFF_X = 0;                 // 49*264 = 12936
constexpr int OFF_Q = 12944;
constexpr int OFF_K = OFF_Q + 64 * HQ;   // 17552
constexpr int OFF_V = OFF_K + 64 * HK;   // 22160
constexpr int OFF_O = OFF_V + 64 * HV;   // 26768
constexpr int HALVES = 39712;            // O ends 39704, align 16B
constexpr int SMEM_BYTES = HALVES * 2 + 256 * 4;   // + proj_b -> 80448 B

// W1 fragments: block (hp,kc,kk,nb,nf) of 32 uint4; q section pre-scaled
__device__ uint4  g_w1f[4 * 8 * 2 * 4 * 3 * 32];   // 384 KB
// Wp fragments: block (kc,kk,nb,nf) of 32 uint4
__device__ uint4  g_wpf[8 * 2 * 4 * 4 * 32];        // 128 KB
__device__ __half g_biash[8 * 49 * 64];             // bias*log2e [h][row][col]

__global__ void prep_kernel(const float* __restrict__ qkv_w,
                            const float* __restrict__ proj_w,
                            const float* __restrict__ bias_table,
                            const int*   __restrict__ rel_idx) {
    const float LOG2E = 1.4426950408889634f;
    const float qs = 0.17677669529663687f * LOG2E;   // scale * log2e
    int t = blockIdx.x * blockDim.x + threadIdx.x;
    if (t < 24576) {
        // --- W1 fragment packing (q section scaled by scale*log2e) ---
        int lane = t & 31;
        int r2 = t >> 5;
        int nf = r2 % 3;  int r3 = r2 / 3;
        int nb = r3 & 3;  int r4 = r3 >> 2;
        int kk = r4 & 1;  int r5 = r4 >> 1;
        int kc = r5 & 7;  int hp = r5 >> 3;
        int h0 = 2 * hp;
        uint32_t wr[4];
        #pragma unroll
        for (int t4 = 0; t4 < 4; t4++) {
            int rowt = (t4 & 2) ? 8 : 0;
            int coft = (t4 & 1) ? 8 : 0;
            int r  = nb * 48 + nf * 16 + rowt + (lane >> 2);   // 0..191
            int gn = (r >> 6) * 256 + (h0 + ((r & 63) >> 5)) * 32 + (r & 31);
            int k  = kc * 32 + kk * 16 + coft + 2 * (lane & 3);
            float f0 = qkv_w[(size_t)k * 768 + gn];
            float f1 = qkv_w[(size_t)(k + 1) * 768 + gn];
            if (r < 64) { f0 *= qs; f1 *= qs; }   // q section
            __half2 hv = __floats2half2_rn(f0, f1);
            wr[t4] = *(uint32_t*)&hv;
        }
        g_w1f[t] = make_uint4(wr[0], wr[1], wr[2], wr[3]);
    } else if (t < 32768) {
        // --- Wp fragment packing: r2 = (kc*2+kk)*16 + nb*4 + nf ---
        int u = t - 24576;
        int lane = u & 31;
        int r2 = u >> 5;
        int nf = r2 & 3;  int r3 = r2 >> 2;
        int nb = r3 & 3;  int r4 = r3 >> 2;
        int kk = r4 & 1;  int kc = r4 >> 1;
        uint32_t wr[4];
        #pragma unroll
        for (int t4 = 0; t4 < 4; t4++) {
            int rowt = (t4 & 2) ? 8 : 0;
            int coft = (t4 & 1) ? 8 : 0;
            int gn = nb * 64 + nf * 16 + rowt + (lane >> 2);
            int k  = kc * 32 + kk * 16 + coft + 2 * (lane & 3);
            __half2 hv = __floats2half2_rn(proj_w[(size_t)k * 256 + gn],
                                           proj_w[(size_t)(k + 1) * 256 + gn]);
            wr[t4] = *(uint32_t*)&hv;
        }
        g_wpf[u] = make_uint4(wr[0], wr[1], wr[2], wr[3]);
    } else {
        // --- bias matrix * log2e (fp16, padding cols = -30000) ---
        int u = t - 32768;
        if (u < 25088) {
            int h = u / 3136, rem = u % 3136;
            int r = rem >> 6, c = rem & 63;
            float v = (c < 49)
                ? bias_table[rel_idx[r * 49 + c] * 8 + h] * LOG2E
                : -30000.0f;
            g_biash[u] = __float2half_rn(v);
        }
    }
}

__device__ __forceinline__ void mma16(float c[4],
                                      uint32_t a0, uint32_t a1, uint32_t a2, uint32_t a3,
                                      uint32_t b0, uint32_t b1) {
    asm volatile(
        "mma.sync.aligned.m16n8k16.row.col.f32.f16.f16.f32 "
        "{%0,%1,%2,%3}, {%4,%5,%6,%7}, {%8,%9}, {%0,%1,%2,%3};"
        : "+f"(c[0]), "+f"(c[1]), "+f"(c[2]), "+f"(c[3])
        : "r"(a0), "r"(a1), "r"(a2), "r"(a3), "r"(b0), "r"(b1));
}
__device__ __forceinline__ void ldsm4(uint32_t r[4], uint32_t a) {
    asm volatile("ldmatrix.sync.aligned.m8n8.x4.shared.b16 {%0,%1,%2,%3}, [%4];"
        : "=r"(r[0]), "=r"(r[1]), "=r"(r[2]), "=r"(r[3]) : "r"(a));
}
__device__ __forceinline__ void ldsm4t(uint32_t r[4], uint32_t a) {
    asm volatile("ldmatrix.sync.aligned.m8n8.x4.trans.shared.b16 {%0,%1,%2,%3}, [%4];"
        : "=r"(r[0]), "=r"(r[1]), "=r"(r[2]), "=r"(r[3]) : "r"(a));
}
__device__ __forceinline__ uint32_t packh2(float x, float y) {
    __half2 h = __floats2half2_rn(x, y);
    return *(uint32_t*)&h;
}

__global__ void __launch_bounds__(256, 2)
win_attn_kernel(const float* __restrict__ x,
                const float* __restrict__ proj_b,
                float*       __restrict__ out) {
    extern __shared__ __half sh[];
    __half* s_x = sh + OFF_X;
    __half* s_q = sh + OFF_Q;
    __half* s_k = sh + OFF_K;
    __half* s_v = sh + OFF_V;   // row-major [token][dim]
    __half* s_o = sh + OFF_O;
    float* s_pb = (float*)((char*)sh + HALVES * 2);
    const uint32_t sb = (uint32_t)__cvta_generic_to_shared(sh);

    const int tid  = threadIdx.x;
    const int w    = tid >> 5;
    const int lane = tid & 31;
    const int g    = lane >> 2;
    const int tg   = lane & 3;
    const int b    = blockIdx.x;

    const int mi = w & 1;          // GEMM1/proj 32-row block
    const int nb = w >> 1;         // GEMM1/proj N block
    const int ahh = w >> 2;        // attention: head within pair
    const int R   = (w & 3) * 16;  // attention: row base

    // ldmatrix lane decomposition
    const int arow_in = (lane & 7) | (((lane >> 3) & 1) << 3);
    const int acol8   = (lane >> 4) << 3;
    const int brow_in = (lane & 7) | (((lane >> 4) & 1) << 3);
    const int bcol8   = ((lane >> 3) & 1) << 3;
    const int vrow_in = lane & 15;
    const int vcol8   = (lane >> 4) << 3;

    // ---- init: stage x (f32->half), proj_b ----
    {
        const float4* x4 = (const float4*)(x + (size_t)b * (NTOK * DIMC));
        #pragma unroll
        for (int i = 0; i < 13; i++) {
            int idx = tid + i * 256;
            if (idx < 3136) {
                int r = idx >> 6, c4 = idx & 63;
                float4 v = x4[idx];
                __half2* dst = (__half2*)&s_x[r * HX + c4 * 4];
                dst[0] = __floats2half2_rn(v.x, v.y);
                dst[1] = __floats2half2_rn(v.z, v.w);
            }
        }
        s_pb[tid] = proj_b[tid];
    }

    // precomputed byte addresses
    uint32_t aXb[2];
    #pragma unroll
    for (int mt = 0; mt < 2; mt++) {
        int r = mi * 32 + mt * 16 + arow_in;
        int rc = (r < 49) ? r : 48;
        aXb[mt] = sb + 2 * (OFF_X + rc * HX + acol8);
    }
    const uint32_t aQb = sb + 2 * (OFF_Q + (R + arow_in) * HQ + ahh * 32 + acol8);
    uint32_t bKb[4];
    #pragma unroll
    for (int nf = 0; nf < 4; nf++)
        bKb[nf] = sb + 2 * (OFF_K + (nf * 16 + brow_in) * HK + ahh * 32 + bcol8);
    uint32_t bVb[2];
    #pragma unroll
    for (int nf = 0; nf < 2; nf++)
        bVb[nf] = sb + 2 * (OFF_V + vrow_in * HV + ahh * 32 + nf * 16 + vcol8);
    uint32_t aOb[2];
    #pragma unroll
    for (int mt = 0; mt < 2; mt++) {
        int r = mi * 32 + mt * 16 + arow_in;
        int rc = (r < 49) ? r : 48;
        aOb[mt] = sb + 2 * (OFF_O + rc * HO + acol8);
    }

    // cross-phase prefetch state: first GEMM1 B fragments of pair hp
    const uint4* wpB = g_w1f + nb * 96 + lane;
    uint4 bv0 = wpB[0], bv1 = wpB[32], bv2 = wpB[64];

    __syncthreads();

    for (int hp = 0; hp < 4; hp++) {
        const int h0 = 2 * hp;

        // ======= GEMM1: qkv_pair[64,192] = x @ W1, B streamed from L2 ======
        float acc1[2][6][4];
        #pragma unroll
        for (int mt = 0; mt < 2; mt++)
            #pragma unroll
            for (int nt = 0; nt < 6; nt++) {
                acc1[mt][nt][0] = 0.f; acc1[mt][nt][1] = 0.f;
                acc1[mt][nt][2] = 0.f; acc1[mt][nt][3] = 0.f;
            }
        {
            const uint4* wp = wpB + (size_t)hp * (16 * 384);
            #pragma unroll
            for (int i = 0; i < 16; i++) {
                uint4 nx0, nx1, nx2;
                if (i < 15) {
                    const uint4* np = wp + (i + 1) * 384;
                    nx0 = np[0]; nx1 = np[32]; nx2 = np[64];
                }
                uint32_t a[2][4];
                ldsm4(a[0], aXb[0] + i * 32);
                ldsm4(a[1], aXb[1] + i * 32);
                mma16(acc1[0][0], a[0][0], a[0][1], a[0][2], a[0][3], bv0.x, bv0.y);
                mma16(acc1[1][0], a[1][0], a[1][1], a[1][2], a[1][3], bv0.x, bv0.y);
                mma16(acc1[0][1], a[0][0], a[0][1], a[0][2], a[0][3], bv0.z, bv0.w);
                mma16(acc1[1][1], a[1][0], a[1][1], a[1][2], a[1][3], bv0.z, bv0.w);
                mma16(acc1[0][2], a[0][0], a[0][1], a[0][2], a[0][3], bv1.x, bv1.y);
                mma16(acc1[1][2], a[1][0], a[1][1], a[1][2], a[1][3], bv1.x, bv1.y);
                mma16(acc1[0][3], a[0][0], a[0][1], a[0][2], a[0][3], bv1.z, bv1.w);
                mma16(acc1[1][3], a[1][0], a[1][1], a[1][2], a[1][3], bv1.z, bv1.w);
                mma16(acc1[0][4], a[0][0], a[0][1], a[0][2], a[0][3], bv2.x, bv2.y);
                mma16(acc1[1][4], a[1][0], a[1][1], a[1][2], a[1][3], bv2.x, bv2.y);
                mma16(acc1[0][5], a[0][0], a[0][1], a[0][2], a[0][3], bv2.z, bv2.w);
                mma16(acc1[1][5], a[1][0], a[1][1], a[1][2], a[1][3], bv2.z, bv2.w);
                if (i < 15) { bv0 = nx0; bv1 = nx1; bv2 = nx2; }
            }
        }
        // barrier: prior pair's scores/PV reads of s_q/k/v must be done
        __syncthreads();
        // scatter q / k / v (uniform: q-scale pre-folded into weights)
        #pragma unroll
        for (int mt = 0; mt < 2; mt++) {
            const int r0 = mi * 32 + mt * 16 + g, r1 = r0 + 8;
            #pragma unroll
            for (int nt = 0; nt < 6; nt++) {
                const int colb = nb * 48 + nt * 8;
                const int s = colb >> 6;
                const int cc = (colb & 63) + 2 * tg;
                __half* d = (s == 0) ? s_q : (s == 1) ? s_k : s_v;
                *(__half2*)&d[r0 * 72 + cc] =
                    __floats2half2_rn(acc1[mt][nt][0], acc1[mt][nt][1]);
                *(__half2*)&d[r1 * 72 + cc] =
                    __floats2half2_rn(acc1[mt][nt][2], acc1[mt][nt][3]);
            }
        }
        __syncthreads();

        // ======= scores: warp = 16 rows x 64 cols of one head ==============
        float sacc[8][4];
        #pragma unroll
        for (int nt = 0; nt < 8; nt++) {
            sacc[nt][0] = 0.f; sacc[nt][1] = 0.f;
            sacc[nt][2] = 0.f; sacc[nt][3] = 0.f;
        }
        #pragma unroll
        for (int kk = 0; kk < 2; kk++) {
            const uint32_t kl = kk * 32;
            uint32_t a[4], bfr[4][4];
            ldsm4(a, aQb + kl);
            ldsm4(bfr[0], bKb[0] + kl);
            ldsm4(bfr[1], bKb[1] + kl);
            ldsm4(bfr[2], bKb[2] + kl);
            ldsm4(bfr[3], bKb[3] + kl);
            #pragma unroll
            for (int nt = 0; nt < 8; nt++)
                mma16(sacc[nt], a[0], a[1], a[2], a[3],
                      bfr[nt >> 1][(nt & 1) * 2], bfr[nt >> 1][(nt & 1) * 2 + 1]);
        }

        // prefetch next pair's first GEMM1 B fragments (hidden by softmax/PV)
        if (hp < 3) {
            const uint4* np = wpB + (size_t)(hp + 1) * (16 * 384);
            bv0 = np[0]; bv1 = np[32]; bv2 = np[64];
        }

        // ======= softmax: exp2 (logits pre-scaled by log2e), no max-sub ====
        // P packed UNNORMALIZED; 1/sum applied at PV output.
        uint32_t pa[4][4];
        float ri0, ri1;
        {
            const int head = h0 + ahh;
            const int row0 = R + g, row1 = R + 8 + g;
            const int rs0 = (row0 < 49) ? row0 : 48;
            const int rs1 = (row1 < 49) ? row1 : 48;
            const __half* b0p = g_biash + (head * 49 + rs0) * 64;
            const __half* b1p = g_biash + (head * 49 + rs1) * 64;
            float sum0 = 0.f, sum1 = 0.f;
            #pragma unroll
            for (int nt = 0; nt < 8; nt++) {
                const int c0 = nt * 8 + 2 * tg;
                float2 bA = __half22float2(*(const __half2*)(b0p + c0));
                float2 bB = __half22float2(*(const __half2*)(b1p + c0));
                float e;
                e = exp2f(sacc[nt][0] + bA.x); sacc[nt][0] = e; sum0 += e;
                e = exp2f(sacc[nt][1] + bA.y); sacc[nt][1] = e; sum0 += e;
                e = exp2f(sacc[nt][2] + bB.x); sacc[nt][2] = e; sum1 += e;
                e = exp2f(sacc[nt][3] + bB.y); sacc[nt][3] = e; sum1 += e;
            }
            // pack P~ immediately (independent of sum reduction)
            #pragma unroll
            for (int kk = 0; kk < 4; kk++) {
                pa[kk][0] = packh2(sacc[2 * kk][0], sacc[2 * kk][1]);
                pa[kk][1] = packh2(sacc[2 * kk][2], sacc[2 * kk][3]);
                pa[kk][2] = packh2(sacc[2 * kk + 1][0], sacc[2 * kk + 1][1]);
                pa[kk][3] = packh2(sacc[2 * kk + 1][2], sacc[2 * kk + 1][3]);
            }
            // sum reduction overlaps PV fragment loads below
            sum0 += __shfl_xor_sync(0xffffffffu, sum0, 1, 4);
            sum0 += __shfl_xor_sync(0xffffffffu, sum0, 2, 4);
            sum1 += __shfl_xor_sync(0xffffffffu, sum1, 1, 4);
            sum1 += __shfl_xor_sync(0xffffffffu, sum1, 2, 4);
            ri0 = 1.0f / sum0;
            ri1 = 1.0f / sum1;
        }

        // ======= O = (P~ @ V) * ri  (V row-major, trans ldmatrix) ==========
        {
            float oacc[4][4];
            #pragma unroll
            for (int nt = 0; nt < 4; nt++) {
                oacc[nt][0] = 0.f; oacc[nt][1] = 0.f;
                oacc[nt][2] = 0.f; oacc[nt][3] = 0.f;
            }
            #pragma unroll
            for (int kk = 0; kk < 4; kk++) {
                const uint32_t kl = kk * (16 * HV * 2);   // 16 token rows
                uint32_t bfr[2][4];
                ldsm4t(bfr[0], bVb[0] + kl);
                ldsm4t(bfr[1], bVb[1] + kl);
                #pragma unroll
                for (int nt = 0; nt < 4; nt++)
                    mma16(oacc[nt], pa[kk][0], pa[kk][1], pa[kk][2], pa[kk][3],
                          bfr[nt >> 1][(nt & 1) * 2], bfr[nt >> 1][(nt & 1) * 2 + 1]);
            }
            const int row0 = R + g, row1 = R + 8 + g;
            const int cb = (h0 + ahh) * 32;
            #pragma unroll
            for (int nt = 0; nt < 4; nt++) {
                const int c = cb + nt * 8 + 2 * tg;
                if (row0 < 49)
                    *(__half2*)&s_o[row0 * HO + c] =
                        __floats2half2_rn(oacc[nt][0] * ri0, oacc[nt][1] * ri0);
                if (row1 < 49)
                    *(__half2*)&s_o[row1 * HO + c] =
                        __floats2half2_rn(oacc[nt][2] * ri1, oacc[nt][3] * ri1);
            }
        }
    } // head pairs

    // hoist proj B i=0 fragments before the barrier (latency hidden)
    const uint4* wpp = g_wpf + nb * 128 + lane;
    uint4 pv0 = wpp[0], pv1 = wpp[32], pv2 = wpp[64], pv3 = wpp[96];
    __syncthreads();   // s_o complete

    // ======= proj: out = O[64,256] @ Wp + b, B streamed from L2 ============
    {
        float facc[2][8][4];
        #pragma unroll
        for (int mt = 0; mt < 2; mt++)
            #pragma unroll
            for (int j = 0; j < 8; j++) {
                facc[mt][j][0] = 0.f; facc[mt][j][1] = 0.f;
                facc[mt][j][2] = 0.f; facc[mt][j][3] = 0.f;
            }
        #pragma unroll
        for (int i = 0; i < 16; i++) {
            uint4 bv0p = pv0, bv1p = pv1, bv2p = pv2, bv3p = pv3;
            if (i < 15) {
                const uint4* bp = wpp + (i + 1) * 512;
                pv0 = bp[0]; pv1 = bp[32]; pv2 = bp[64]; pv3 = bp[96];
            }
            uint32_t a[2][4];
            ldsm4(a[0], aOb[0] + i * 32);
            ldsm4(a[1], aOb[1] + i * 32);
            mma16(facc[0][0], a[0][0], a[0][1], a[0][2], a[0][3], bv0p.x, bv0p.y);
            mma16(facc[1][0], a[1][0], a[1][1], a[1][2], a[1][3], bv0p.x, bv0p.y);
            mma16(facc[0][1], a[0][0], a[0][1], a[0][2], a[0][3], bv0p.z, bv0p.w);
            mma16(facc[1][1], a[1][0], a[1][1], a[1][2], a[1][3], bv0p.z, bv0p.w);
            mma16(facc[0][2], a[0][0], a[0][1], a[0][2], a[0][3], bv1p.x, bv1p.y);
            mma16(facc[1][2], a[1][0], a[1][1], a[1][2], a[1][3], bv1p.x, bv1p.y);
            mma16(facc[0][3], a[0][0], a[0][1], a[0][2], a[0][3], bv1p.z, bv1p.w);
            mma16(facc[1][3], a[1][0], a[1][1], a[1][2], a[1][3], bv1p.z, bv1p.w);
            mma16(facc[0][4], a[0][0], a[0][1], a[0][2], a[0][3], bv2p.x, bv2p.y);
            mma16(facc[1][4], a[1][0], a[1][1], a[1][2], a[1][3], bv2p.x, bv2p.y);
            mma16(facc[0][5], a[0][0], a[0][1], a[0][2], a[0][3], bv2p.z, bv2p.w);
            mma16(facc[1][5], a[1][0], a[1][1], a[1][2], a[1][3], bv2p.z, bv2p.w);
            mma16(facc[0][6], a[0][0], a[0][1], a[0][2], a[0][3], bv3p.x, bv3p.y);
            mma16(facc[1][6], a[1][0], a[1][1], a[1][2], a[1][3], bv3p.x, bv3p.y);
            mma16(facc[0][7], a[0][0], a[0][1], a[0][2], a[0][3], bv3p.z, bv3p.w);
            mma16(facc[1][7], a[1][0], a[1][1], a[1][2], a[1][3], bv3p.z, bv3p.w);
        }
        // epilogue
        float* ob = out + (size_t)b * (NTOK * DIMC);
        #pragma unroll
        for (int mt = 0; mt < 2; mt++) {
            const int r0 = mi * 32 + mt * 16 + g, r1 = r0 + 8;
            #pragma unroll
            for (int nt = 0; nt < 8; nt++) {
                const int c = nb * 64 + nt * 8 + 2 * tg;
                if (r0 < NTOK) {
                    float2 v;
                    v.x = facc[mt][nt][0] + s_pb[c];
                    v.y = facc[mt][nt][1] + s_pb[c + 1];
                    *(float2*)(ob + r0 * DIMC + c) = v;
                }
                if (r1 < NTOK) {
                    float2 v;
                    v.x = facc[mt][nt][2] + s_pb[c];
                    v.y = facc[mt][nt][3] + s_pb[c + 1];
                    *(float2*)(ob + r1 * DIMC + c) = v;
                }
            }
        }
    }
}

extern "C" void kernel_launch(void* const* d_in, const int* in_sizes, int n_in,
                              void* d_out, int out_size) {
    (void)in_sizes; (void)n_in; (void)out_size;
    const float* x      = (const float*)d_in[0];
    const float* qkv_w  = (const float*)d_in[1];
    const float* proj_w = (const float*)d_in[2];
    const float* proj_b = (const float*)d_in[3];
    const float* bt     = (const float*)d_in[4];
    const int*   ri     = (const int*)d_in[5];
    float* out = (float*)d_out;

    prep_kernel<<<226, 256>>>(qkv_w, proj_w, bt, ri);
    cudaFuncSetAttribute(win_attn_kernel,
                         cudaFuncAttributeMaxDynamicSharedMemorySize, SMEM_BYTES);
    win_attn_kernel<<<4096, 256, SMEM_BYTES>>>(x, proj_b, out);
}